// round 11
// baseline (speedup 1.0000x reference)
#include <cuda_runtime.h>

#define Wd 512
#define Hd 512
#define W2 (Wd / 2)
#define NT 256
#define RSTRIP 64
#define THIRD 0.3333333333333333f
#define EPS 0.01f

typedef unsigned long long ull;

static __device__ __forceinline__ ull U(float2 v) { ull r; memcpy(&r, &v, 8); return r; }
static __device__ __forceinline__ float2 F(ull u) { float2 v; memcpy(&v, &u, 8); return v; }

static __device__ __forceinline__ float2 f2add(float2 a, float2 b) {
    ull r; asm("add.rn.f32x2 %0,%1,%2;" : "=l"(r) : "l"(U(a)), "l"(U(b))); return F(r);
}
static __device__ __forceinline__ float2 f2mul(float2 a, float2 b) {
    ull r; asm("mul.rn.f32x2 %0,%1,%2;" : "=l"(r) : "l"(U(a)), "l"(U(b))); return F(r);
}
static __device__ __forceinline__ float2 f2fma(float2 a, float2 b, float2 c) {
    ull r; asm("fma.rn.f32x2 %0,%1,%2,%3;" : "=l"(r) : "l"(U(a)), "l"(U(b)), "l"(U(c))); return F(r);
}
static __device__ __forceinline__ float2 mk2(float a, float b) { float2 v; v.x = a; v.y = b; return v; }

// boundary exchange: bnd[buf][field][slot], slot = warp+1, slots 0 and 9 are
// permanent zeros (global image edges). fields: 0 Iy,1 Ix,2 Py,3 Px,4 Ay,5 Ax,6 By,7 Bx
__global__ __launch_bounds__(NT, 4)
void gf_kernel(const float* __restrict__ gI, const float* __restrict__ gP,
               float* __restrict__ gO)
{
    __shared__ float bnd[2][8][10];

    const int t = threadIdx.x;
    const int w = t >> 5;
    const int l = t & 31;
    const int y0 = blockIdx.x * RSTRIP;
    const size_t base = (size_t)blockIdx.y * (size_t)(Wd * Hd);
    const float2* __restrict__ GI = (const float2*)(gI + base);
    const float2* __restrict__ GP = (const float2*)(gP + base);
    float2* __restrict__ GO = (float2*)(gO + base);

    const float icx0 = (t == 0)      ? 0.5f : THIRD;   // count_include_pad=False col counts
    const float icx1 = (t == NT - 1) ? 0.5f : THIRD;

    // permanent zero guards at slots 0 and 9 (both buffers, all 8 fields)
    if (t < 32) {
        const int b = t & 1, f = (t >> 1) & 7, j = ((t >> 4) & 1) ? 9 : 0;
        bnd[b][f][j] = 0.f;
    }

    const float2 z2 = mk2(0.f, 0.f);

    // vertical sliding state (pair-sum ps + last h-row l), packed float2
    float2 psI = z2, lI = z2, psP = z2, lP = z2;
    float2 psII = z2, lII = z2, psIP = z2, lIP = z2;
    float2 psA = z2, lA = z2, psB = z2, lB = z2;
    float2 avP = z2, bvP = z2;

    // prologue rows y0-2 (cur) and y0-1 (next)
    float2 viC = z2, vpC = z2, viN = z2, vpN = z2;
    if (y0 >= 2) {
        viC = GI[(y0 - 2) * W2 + t]; vpC = GP[(y0 - 2) * W2 + t];
        viN = GI[(y0 - 1) * W2 + t]; vpN = GP[(y0 - 1) * W2 + t];
    }
    // stage boundaries for row viC into buffer 0 (A/B rows start as zero)
    if (l == 31) { bnd[0][0][w + 1] = viC.y; bnd[0][2][w + 1] = vpC.y;
                   bnd[0][4][w + 1] = 0.f;   bnd[0][6][w + 1] = 0.f; }
    if (l == 0)  { bnd[0][1][w + 1] = viC.x; bnd[0][3][w + 1] = vpC.x;
                   bnd[0][5][w + 1] = 0.f;   bnd[0][7][w + 1] = 0.f; }
    __syncthreads();

    int rn   = y0;            // row prefetched this body
    int ra   = y0 - 3;        // a/b row produced this body
    int ro   = y0 - 5;        // output row produced this body
    int oidx = y0 * W2 + t;   // output index (advances in main bodies)

#define BODY(P, DO_OUT)                                                          \
    {                                                                            \
        /* horizontal neighbors via warp shuffle; warp edges from smem */        \
        float iLs = __shfl_up_sync(0xffffffffu, viC.y, 1);                       \
        float iRs = __shfl_down_sync(0xffffffffu, viC.x, 1);                     \
        float pLs = __shfl_up_sync(0xffffffffu, vpC.y, 1);                       \
        float pRs = __shfl_down_sync(0xffffffffu, vpC.x, 1);                     \
        float aLs = __shfl_up_sync(0xffffffffu, avP.y, 1);                       \
        float aRs = __shfl_down_sync(0xffffffffu, avP.x, 1);                     \
        float bLs = __shfl_up_sync(0xffffffffu, bvP.y, 1);                       \
        float bRs = __shfl_down_sync(0xffffffffu, bvP.x, 1);                     \
        if (l == 0)  { iLs = bnd[P][0][w];     pLs = bnd[P][2][w];               \
                       aLs = bnd[P][4][w];     bLs = bnd[P][6][w]; }             \
        if (l == 31) { iRs = bnd[P][1][w + 2]; pRs = bnd[P][3][w + 2];           \
                       aRs = bnd[P][5][w + 2]; bRs = bnd[P][7][w + 2]; }         \
        /* prefetch input row rn (consumed 2 bodies later) */                    \
        float2 viF = z2, vpF = z2;                                               \
        if (rn < Hd) { viF = GI[rn * W2 + t]; vpF = GP[rn * W2 + t]; }           \
        rn++;                                                                    \
        /* shifted pairs for row viC/vpC */                                      \
        const float2 sLI = mk2(iLs, viC.x), sRI = mk2(viC.y, iRs);               \
        const float2 sLP = mk2(pLs, vpC.x), sRP = mk2(vpC.y, pRs);               \
        /* horizontal 3-sums (packed f32x2) */                                   \
        const float2 hI  = f2add(f2add(sLI, viC), sRI);                          \
        const float2 hP  = f2add(f2add(sLP, vpC), sRP);                          \
        const float2 hII = f2fma(sLI, sLI, f2fma(viC, viC, f2mul(sRI, sRI)));    \
        const float2 hIP = f2fma(sLI, sLP, f2fma(viC, vpC, f2mul(sRI, sRP)));    \
        /* vertical 3-row slide (packed) */                                      \
        const float2 SI  = f2add(psI,  hI);  psI  = f2add(lI,  hI);  lI  = hI;   \
        const float2 SP  = f2add(psP,  hP);  psP  = f2add(lP,  hP);  lP  = hP;   \
        const float2 SII = f2add(psII, hII); psII = f2add(lII, hII); lII = hII;  \
        const float2 SIP = f2add(psIP, hIP); psIP = f2add(lIP, hIP); lIP = hIP;  \
        /* a,b for row ra; rows outside [0,Hd) MUST be zero */                   \
        const float invcyA = (ra == 0 || ra == Hd - 1) ? 0.5f : THIRD;           \
        const bool raOK = ((unsigned)ra < (unsigned)Hd);                         \
        ra++;                                                                    \
        float2 av = z2, bv = z2;                                                 \
        if (raOK) {                                                              \
            {                                                                    \
                const float inv = icx0 * invcyA;                                 \
                const float mI = SI.x * inv, mP = SP.x * inv;                    \
                const float var = fmaf(SII.x, inv, -mI * mI);                    \
                const float cov = fmaf(SIP.x, inv, -mI * mP);                    \
                const float a = __fdividef(cov, var + EPS);                      \
                av.x = a; bv.x = fmaf(-a, mI, mP);                               \
            }                                                                    \
            {                                                                    \
                const float inv = icx1 * invcyA;                                 \
                const float mI = SI.y * inv, mP = SP.y * inv;                    \
                const float var = fmaf(SII.y, inv, -mI * mI);                    \
                const float cov = fmaf(SIP.y, inv, -mI * mP);                    \
                const float a = __fdividef(cov, var + EPS);                      \
                av.y = a; bv.y = fmaf(-a, mI, mP);                               \
            }                                                                    \
        }                                                                        \
        /* a/b h-sums for row staged last body (avP) + vertical slide */         \
        const float2 sLA = mk2(aLs, avP.x), sRA = mk2(avP.y, aRs);               \
        const float2 sLB = mk2(bLs, bvP.x), sRB = mk2(bvP.y, bRs);               \
        const float2 hA = f2add(f2add(sLA, avP), sRA);                           \
        const float2 hB = f2add(f2add(sLB, bvP), sRB);                           \
        const float2 SA = f2add(psA, hA); psA = f2add(lA, hA); lA = hA;          \
        const float2 SB = f2add(psB, hB); psB = f2add(lB, hB); lB = hB;          \
        /* output row ro */                                                      \
        if (DO_OUT) {                                                            \
            const float invcyO = (ro == 0 || ro == Hd - 1) ? 0.5f : THIRD;       \
            const float2 vO = __ldg(&GI[oidx]);                                  \
            const float2 sc = mk2(icx0 * invcyO, icx1 * invcyO);                 \
            GO[oidx] = f2mul(f2fma(SA, vO, SB), sc);                             \
            oidx += W2;                                                          \
        }                                                                        \
        ro++;                                                                    \
        /* stage boundaries for next body: row viN and this body's a/b row */    \
        if (l == 31) { bnd[P ^ 1][0][w + 1] = viN.y; bnd[P ^ 1][2][w + 1] = vpN.y; \
                       bnd[P ^ 1][4][w + 1] = av.y;  bnd[P ^ 1][6][w + 1] = bv.y; } \
        if (l == 0)  { bnd[P ^ 1][1][w + 1] = viN.x; bnd[P ^ 1][3][w + 1] = vpN.x; \
                       bnd[P ^ 1][5][w + 1] = av.x;  bnd[P ^ 1][7][w + 1] = bv.x; } \
        avP = av; bvP = bv;                                                      \
        viC = viN; vpC = vpN; viN = viF; vpN = vpF;                              \
        __syncthreads();                                                         \
    }

    // prologue: i = 0..4 (no outputs), parities 0,1,0,1,0
    BODY(0, false) BODY(1, false) BODY(0, false) BODY(1, false) BODY(0, false)

    // main: i = 5..68 (64 outputs), parities 1,0 repeated
    for (int k = 0; k < 32; ++k) {
        BODY(1, true)
        BODY(0, true)
    }
#undef BODY
}

extern "C" void kernel_launch(void* const* d_in, const int* in_sizes, int n_in,
                              void* d_out, int out_size) {
    const float* I = (const float*)d_in[0];   // input
    const float* P = (const float*)d_in[1];   // guide
    float* O = (float*)d_out;

    const int Z = in_sizes[0] / (Wd * Hd);    // B*C = 128
    dim3 block(NT, 1, 1);
    dim3 grid(Hd / RSTRIP, Z, 1);             // 8 x 128
    gf_kernel<<<grid, block>>>(I, P, O);
}

// round 12
// speedup vs baseline: 1.0164x; 1.0164x over previous
#include <cuda_runtime.h>

#define Wd 512
#define Hd 512
#define W2 (Wd / 2)
#define NT 256
#define RSTRIP 64
#define THIRD 0.3333333333333333f
#define EPS 0.01f

typedef unsigned long long ull;

static __device__ __forceinline__ ull U(float2 v) { ull r; memcpy(&r, &v, 8); return r; }
static __device__ __forceinline__ float2 F(ull u) { float2 v; memcpy(&v, &u, 8); return v; }

static __device__ __forceinline__ float2 f2add(float2 a, float2 b) {
    ull r; asm("add.rn.f32x2 %0,%1,%2;" : "=l"(r) : "l"(U(a)), "l"(U(b))); return F(r);
}
static __device__ __forceinline__ float2 f2mul(float2 a, float2 b) {
    ull r; asm("mul.rn.f32x2 %0,%1,%2;" : "=l"(r) : "l"(U(a)), "l"(U(b))); return F(r);
}
static __device__ __forceinline__ float2 f2fma(float2 a, float2 b, float2 c) {
    ull r; asm("fma.rn.f32x2 %0,%1,%2,%3;" : "=l"(r) : "l"(U(a)), "l"(U(b)), "l"(U(c))); return F(r);
}
static __device__ __forceinline__ float2 mk2(float a, float b) { float2 v; v.x = a; v.y = b; return v; }

__global__ __launch_bounds__(NT, 4)
void gf_kernel(const float* __restrict__ gI, const float* __restrict__ gP,
               float* __restrict__ gO)
{
    // packed exchange rows: sIP[buf][slot] = {i0,i1,p0,p1} of thread slot-1,
    // sAB likewise {a0,a1,b0,b1}. slots 0 and NT+1 are permanent zero guards.
    __shared__ __align__(16) float4 sIP[2][NT + 2], sAB[2][NT + 2];

    const int t  = threadIdx.x;
    const int y0 = blockIdx.x * RSTRIP;
    const size_t base = (size_t)blockIdx.y * (size_t)(Wd * Hd);
    const float2* __restrict__ GI = (const float2*)(gI + base);
    const float2* __restrict__ GP = (const float2*)(gP + base);
    float2* __restrict__ GO = (float2*)(gO + base);

    const float icx0 = (t == 0)      ? 0.5f : THIRD;   // count_include_pad=False col counts
    const float icx1 = (t == NT - 1) ? 0.5f : THIRD;

    // permanent zero guards: 2 buffers x 2 arrays x 2 slots
    if (t < 8) {
        const int b = t & 1;
        const int s = (t & 2) ? (NT + 1) : 0;
        const float4 z4 = make_float4(0.f, 0.f, 0.f, 0.f);
        if (t & 4) sAB[b][s] = z4; else sIP[b][s] = z4;
    }

    const float2 z2 = mk2(0.f, 0.f);

    // vertical sliding state (pair-sum ps + last h-row l), packed float2
    float2 psI = z2, lI = z2, psP = z2, lP = z2;
    float2 psII = z2, lII = z2, psIP = z2, lIP = z2;
    float2 psA = z2, lA = z2, psB = z2, lB = z2;
    float2 avP = z2, bvP = z2;

    // prologue rows y0-2 (cur) and y0-1 (next)
    float2 viC = z2, vpC = z2, viN = z2, vpN = z2;
    if (y0 >= 2) {
        viC = GI[(y0 - 2) * W2 + t]; vpC = GP[(y0 - 2) * W2 + t];
        viN = GI[(y0 - 1) * W2 + t]; vpN = GP[(y0 - 1) * W2 + t];
    }
    sIP[0][t + 1] = make_float4(viC.x, viC.y, vpC.x, vpC.y);
    sAB[0][t + 1] = make_float4(0.f, 0.f, 0.f, 0.f);
    __syncthreads();

    int rn   = y0;            // row prefetched this body
    int ra   = y0 - 3;        // a/b row produced this body
    int ro   = y0 - 5;        // output row produced this body
    int oidx = y0 * W2 + t;   // output / output-I index (advances in main bodies)

#define BODY(P, DO_OUT)                                                          \
    {                                                                            \
        /* neighbor reads: 4x LDS.128, guards make global edges zero */         \
        const float4 vLIP = sIP[P][t];                                           \
        const float4 vRIP = sIP[P][t + 2];                                       \
        const float4 vLAB = sAB[P][t];                                           \
        const float4 vRAB = sAB[P][t + 2];                                       \
        /* prefetch input row rn (consumed 2 bodies later) */                    \
        float2 viF = z2, vpF = z2;                                               \
        if (rn < Hd) { viF = GI[rn * W2 + t]; vpF = GP[rn * W2 + t]; }           \
        rn++;                                                                    \
        /* shifted pairs for row viC/vpC */                                      \
        const float2 sLI = mk2(vLIP.y, viC.x), sRI = mk2(viC.y, vRIP.x);         \
        const float2 sLP = mk2(vLIP.w, vpC.x), sRP = mk2(vpC.y, vRIP.z);         \
        /* horizontal 3-sums (packed f32x2) */                                   \
        const float2 hI  = f2add(f2add(sLI, viC), sRI);                          \
        const float2 hP  = f2add(f2add(sLP, vpC), sRP);                          \
        const float2 hII = f2fma(sLI, sLI, f2fma(viC, viC, f2mul(sRI, sRI)));    \
        const float2 hIP = f2fma(sLI, sLP, f2fma(viC, vpC, f2mul(sRI, sRP)));    \
        /* vertical 3-row slide (packed) */                                      \
        const float2 SI  = f2add(psI,  hI);  psI  = f2add(lI,  hI);  lI  = hI;   \
        const float2 SP  = f2add(psP,  hP);  psP  = f2add(lP,  hP);  lP  = hP;   \
        const float2 SII = f2add(psII, hII); psII = f2add(lII, hII); lII = hII;  \
        const float2 SIP = f2add(psIP, hIP); psIP = f2add(lIP, hIP); lIP = hIP;  \
        /* a,b for row ra; rows outside [0,Hd) MUST be zero */                   \
        const float invcyA = (ra == 0 || ra == Hd - 1) ? 0.5f : THIRD;           \
        const bool raOK = ((unsigned)ra < (unsigned)Hd);                         \
        ra++;                                                                    \
        float2 av = z2, bv = z2;                                                 \
        if (raOK) {                                                              \
            {                                                                    \
                const float inv = icx0 * invcyA;                                 \
                const float mI = SI.x * inv, mP = SP.x * inv;                    \
                const float var = fmaf(SII.x, inv, -mI * mI);                    \
                const float cov = fmaf(SIP.x, inv, -mI * mP);                    \
                const float a = __fdividef(cov, var + EPS);                      \
                av.x = a; bv.x = fmaf(-a, mI, mP);                               \
            }                                                                    \
            {                                                                    \
                const float inv = icx1 * invcyA;                                 \
                const float mI = SI.y * inv, mP = SP.y * inv;                    \
                const float var = fmaf(SII.y, inv, -mI * mI);                    \
                const float cov = fmaf(SIP.y, inv, -mI * mP);                    \
                const float a = __fdividef(cov, var + EPS);                      \
                av.y = a; bv.y = fmaf(-a, mI, mP);                               \
            }                                                                    \
        }                                                                        \
        /* a/b h-sums for row staged last body (avP) + vertical slide */         \
        const float2 sLA = mk2(vLAB.y, avP.x), sRA = mk2(avP.y, vRAB.x);         \
        const float2 sLB = mk2(vLAB.w, bvP.x), sRB = mk2(bvP.y, vRAB.z);         \
        const float2 hA = f2add(f2add(sLA, avP), sRA);                           \
        const float2 hB = f2add(f2add(sLB, bvP), sRB);                           \
        const float2 SA = f2add(psA, hA); psA = f2add(lA, hA); lA = hA;          \
        const float2 SB = f2add(psB, hB); psB = f2add(lB, hB); lB = hB;          \
        /* output row ro */                                                      \
        if (DO_OUT) {                                                            \
            const float invcyO = (ro == 0 || ro == Hd - 1) ? 0.5f : THIRD;       \
            const float2 vO = __ldg(&GI[oidx]);                                  \
            const float2 sc = mk2(icx0 * invcyO, icx1 * invcyO);                 \
            GO[oidx] = f2mul(f2fma(SA, vO, SB), sc);                             \
            oidx += W2;                                                          \
        }                                                                        \
        ro++;                                                                    \
        /* stage next buffer: 2x STS.128 */                                      \
        sIP[P ^ 1][t + 1] = make_float4(viN.x, viN.y, vpN.x, vpN.y);             \
        sAB[P ^ 1][t + 1] = make_float4(av.x, av.y, bv.x, bv.y);                 \
        avP = av; bvP = bv;                                                      \
        viC = viN; vpC = vpN; viN = viF; vpN = vpF;                              \
        __syncthreads();                                                         \
    }

    // prologue: i = 0..4 (no outputs), parities 0,1,0,1,0
    BODY(0, false) BODY(1, false) BODY(0, false) BODY(1, false) BODY(0, false)

    // main: i = 5..68 (64 outputs), parities 1,0 repeated
    for (int k = 0; k < 32; ++k) {
        BODY(1, true)
        BODY(0, true)
    }
#undef BODY
}

extern "C" void kernel_launch(void* const* d_in, const int* in_sizes, int n_in,
                              void* d_out, int out_size) {
    const float* I = (const float*)d_in[0];   // input
    const float* P = (const float*)d_in[1];   // guide
    float* O = (float*)d_out;

    const int Z = in_sizes[0] / (Wd * Hd);    // B*C = 128
    dim3 block(NT, 1, 1);
    dim3 grid(Hd / RSTRIP, Z, 1);             // 8 x 128
    gf_kernel<<<grid, block>>>(I, P, O);
}